// round 12
// baseline (speedup 1.0000x reference)
#include <cuda_runtime.h>

#define T_LEN  1024
#define NSTEP  1023
#define B_SZ   8192

typedef unsigned long long ull;

// scratch: time-major inputs
__device__ int   g_act_t[T_LEN * B_SZ];            // [t][b]
__device__ float g_rew_t[T_LEN * B_SZ];            // [t][b]

// ---------------- packed f32x2 helpers ----------------
__device__ __forceinline__ void ffma2(ull& d, ull a, ull b) {
    asm("fma.rn.f32x2 %0, %1, %2, %0;" : "+l"(d) : "l"(a), "l"(b));
}
__device__ __forceinline__ ull mul2(ull a, ull b) {
    ull r; asm("mul.rn.f32x2 %0, %1, %2;" : "=l"(r) : "l"(a), "l"(b)); return r;
}
__device__ __forceinline__ ull pack2(float x, float y) {
    ull r; asm("mov.b64 %0, {%1, %2};" : "=l"(r) : "f"(x), "f"(y)); return r;
}
__device__ __forceinline__ float2 unpack2(ull v) {
    float2 r; asm("mov.b64 {%0, %1}, %2;" : "=f"(r.x), "=f"(r.y) : "l"(v)); return r;
}
// input pre-scaled by 2*log2(e):  tanh = 1 - 2/(2^x' + 1)   (~1e-6 abs err)
__device__ __forceinline__ float tanh_pre(float xs) {
    float e, r;
    asm("ex2.approx.f32 %0, %1;" : "=f"(e) : "f"(xs));
    asm("rcp.approx.f32 %0, %1;" : "=f"(r) : "f"(e + 1.0f));
    return fmaf(-2.0f, r, 1.0f);
}
#define TANH_SC 2.8853900817779268f   // 2*log2(e)

// ---------------- transpose [B][T] -> [T][B]  +  zero(out) ----------------
__global__ void __launch_bounds__(256)
transpose_kernel(const int* __restrict__ act, const float* __restrict__ rew,
                 float* __restrict__ out) {
    const int tx = threadIdx.x, ty = threadIdx.y;
    if (blockIdx.z == 2) {
        const size_t base =
            ((size_t)blockIdx.y * gridDim.x + blockIdx.x) * (size_t)NSTEP;
        float4* o4 = (float4*)out;
        const float4 z = make_float4(0.f, 0.f, 0.f, 0.f);
        const int tid = ty * 32 + tx;
        for (int i = tid; i < NSTEP; i += 256) o4[base + i] = z;
        return;
    }
    __shared__ unsigned tile[32][33];
    const int tt = blockIdx.x * 32, tb = blockIdx.y * 32;
    const unsigned* src = (blockIdx.z == 0) ? (const unsigned*)act : (const unsigned*)rew;
    unsigned*       dst = (blockIdx.z == 0) ? (unsigned*)g_act_t  : (unsigned*)g_rew_t;
    #pragma unroll
    for (int i = 0; i < 32; i += 8)
        tile[ty + i][tx] = src[(long long)(tb + ty + i) * T_LEN + tt + tx];
    __syncthreads();
    #pragma unroll
    for (int i = 0; i < 32; i += 8)
        dst[(long long)(tt + ty + i) * B_SZ + tb + tx] = tile[tx][ty + i];
}

// ---------------- main recurrent kernel ----------------
// LANE-PER-ELEMENT, all-uniform weights. grid = 128 CTAs x 128 thr (4 warps,
// one per SMSP). CTAs 0..63: reward module; 64..127: action module. Each lane
// owns one batch element: its full 32-dim state lives in 16 f32x2 registers.
// ALL weight reads are single-address warp-uniform SMEM broadcasts (1 wavefront
// each); zero shuffles; rows processed in 2 passes of 16 to cap register
// pressure (acc[16] per pass). Outputs via atomicAdd into the zeroed out.
__global__ void __launch_bounds__(128)
memann_mod(const float* __restrict__ w_r1, const float* __restrict__ b_r1,
           const float* __restrict__ w_r2, const float* __restrict__ b_r2,
           const float* __restrict__ w_a1, const float* __restrict__ b_a1,
           const float* __restrict__ w_a2, const float* __restrict__ b_a2,
           float*       __restrict__ out)
{
    // first-layer weights, prescaled, row-major dim-pairs: w1u[r][p]={w[r][2p],w[r][2p+1]}
    __shared__ __align__(16) ull w1u[32][16];
    __shared__ __align__(16) ull bwu[32];          // reward: {b_r1', w_r1[.,0]'} per row
    __shared__ __align__(16) ull w2u[16];          // w_r2 dim-pairs (unscaled)
    // action one-hot bias {v,0},{v,0} per row-pair, a as FAST index (lanes
    // diverge over a within 64B -> ~1 wavefront)
    __shared__ __align__(16) ulonglong2 cba[16][4];
    __shared__ __align__(16) ull wa2u[4][16];      // w_a2 rows, dim-pairs (unscaled)
    __shared__ float sc[5];                         // b_r2, b_a2[0..3]

    const int tid = threadIdx.x;
    const bool is_rew = blockIdx.x < 64;

    // ---- one-time staging ----
    if (is_rew) {
        #pragma unroll
        for (int kk = 0; kk < 4; kk++) {
            const int i = tid * 4 + kk;            // 512 ull
            const int r = i >> 4, p = i & 15;
            w1u[r][p] = pack2(w_r1[r * 33 + 1 + 2 * p] * TANH_SC,
                              w_r1[r * 33 + 2 + 2 * p] * TANH_SC);
        }
        if (tid < 32)
            bwu[tid] = pack2(b_r1[tid] * TANH_SC, w_r1[tid * 33] * TANH_SC);
        if (tid >= 32 && tid < 48) {
            const int p = tid - 32;
            w2u[p] = pack2(w_r2[2 * p], w_r2[2 * p + 1]);
        }
        if (tid == 48) sc[0] = b_r2[0];
    } else {
        #pragma unroll
        for (int kk = 0; kk < 4; kk++) {
            const int i = tid * 4 + kk;
            const int r = i >> 4, p = i & 15;
            w1u[r][p] = pack2(w_a1[r * 36 + 4 + 2 * p] * TANH_SC,
                              w_a1[r * 36 + 5 + 2 * p] * TANH_SC);
        }
        {   // cba[j][a]: .x={colb'[2j],0} .y={colb'[2j+1],0}
            const int j = tid >> 3, a = (tid >> 1) & 3, comp = tid & 1;
            const int row = 2 * j + comp;
            ((ull*)&cba[j][a])[comp] =
                pack2((w_a1[row * 36 + a] + b_a1[row]) * TANH_SC, 0.0f);
        }
        if (tid < 64) {
            const int k = tid >> 4, p = tid & 15;
            wa2u[k][p] = pack2(w_a2[k * 32 + 2 * p], w_a2[k * 32 + 2 * p + 1]);
        }
        if (tid >= 64 && tid < 68) sc[1 + tid - 64] = b_a2[tid - 64];
    }
    __syncthreads();

    const long long b = (long long)(is_rew ? blockIdx.x : blockIdx.x - 64) * 128 + tid;
    const int*   ap = g_act_t + b;
    const float* rp = g_rew_t + b;
    float* op = out + (size_t)b * (NSTEP * 4);

    ull s[16];                                     // full 32-dim state, dim-pairs
    #pragma unroll
    for (int p = 0; p < 16; p++) s[p] = 0ull;

    if (is_rew) {
        // ================= reward module =================
        const float br2 = sc[0];
        float q0 = 0.f, q1 = 0.f, q2 = 0.f, q3 = 0.f;
        int   a_cur = ap[0];
        float r_cur = rp[0];

        for (int t = 0; t < NSTEP; t++) {
            const int   a_nxt = ap[(t + 1) * B_SZ];
            const float r_nxt = rp[(t + 1) * B_SZ];
            const ull   rv    = pack2(1.0f, r_cur);

            ull ns[8];                              // pass-0 results (dims 0..15)
            #pragma unroll
            for (int p = 0; p < 2; p++) {
                ull acc[16];
                #pragma unroll
                for (int r2 = 0; r2 < 8; r2++) {    // init {b', w0'*r}
                    const ulonglong2 bw = *(const ulonglong2*)&bwu[p * 16 + 2 * r2];
                    acc[2 * r2]     = mul2(bw.x, rv);
                    acc[2 * r2 + 1] = mul2(bw.y, rv);
                }
                #pragma unroll
                for (int pp = 0; pp < 8; pp++) {    // dims 4pp..4pp+3
                    const ull s0 = s[2 * pp], s1 = s[2 * pp + 1];
                    #pragma unroll
                    for (int r = 0; r < 16; r++) {
                        const ulonglong2 w =
                            *(const ulonglong2*)&w1u[p * 16 + r][2 * pp];
                        ffma2(acc[r], w.x, s0);
                        ffma2(acc[r], w.y, s1);
                    }
                }
                #pragma unroll
                for (int r2 = 0; r2 < 8; r2++) {
                    const float2 u0 = unpack2(acc[2 * r2]);
                    const float2 u1 = unpack2(acc[2 * r2 + 1]);
                    const ull nv = pack2(tanh_pre(u0.x + u0.y),
                                         tanh_pre(u1.x + u1.y));
                    if (p == 0) ns[r2] = nv; else s[8 + r2] = nv;
                }
            }
            #pragma unroll
            for (int r2 = 0; r2 < 8; r2++) s[r2] = ns[r2];

            // q_new = w_r2 . s + b_r2 (fully in-lane, uniform weight loads)
            ull qa = 0ull;
            #pragma unroll
            for (int pq = 0; pq < 8; pq++) {
                const ulonglong2 w = *(const ulonglong2*)&w2u[2 * pq];
                ffma2(qa, w.x, s[2 * pq]);
                ffma2(qa, w.y, s[2 * pq + 1]);
            }
            const float2 qf = unpack2(qa);
            const float q_new = qf.x + qf.y + br2;

            q0 = (a_cur == 0) ? q_new : q0 * 0.95f;
            q1 = (a_cur == 1) ? q_new : q1 * 0.95f;
            q2 = (a_cur == 2) ? q_new : q2 * 0.95f;
            q3 = (a_cur == 3) ? q_new : q3 * 0.95f;
            atomicAdd(op + (size_t)t * 4,     q0);
            atomicAdd(op + (size_t)t * 4 + 1, q1);
            atomicAdd(op + (size_t)t * 4 + 2, q2);
            atomicAdd(op + (size_t)t * 4 + 3, q3);

            a_cur = a_nxt; r_cur = r_nxt;
        }
    } else {
        // ================= action-history module =================
        const float ba0 = sc[1], ba1 = sc[2], ba2v = sc[3], ba3 = sc[4];
        int a_cur = ap[0];

        for (int t = 0; t < NSTEP; t++) {
            const int a_nxt = ap[(t + 1) * B_SZ];

            ull ns[8];
            #pragma unroll
            for (int p = 0; p < 2; p++) {
                ull acc[16];
                #pragma unroll
                for (int r2 = 0; r2 < 8; r2++) {    // init from one-hot column
                    const ulonglong2 cb = cba[p * 8 + r2][a_cur];
                    acc[2 * r2]     = cb.x;
                    acc[2 * r2 + 1] = cb.y;
                }
                #pragma unroll
                for (int pp = 0; pp < 8; pp++) {
                    const ull s0 = s[2 * pp], s1 = s[2 * pp + 1];
                    #pragma unroll
                    for (int r = 0; r < 16; r++) {
                        const ulonglong2 w =
                            *(const ulonglong2*)&w1u[p * 16 + r][2 * pp];
                        ffma2(acc[r], w.x, s0);
                        ffma2(acc[r], w.y, s1);
                    }
                }
                #pragma unroll
                for (int r2 = 0; r2 < 8; r2++) {
                    const float2 u0 = unpack2(acc[2 * r2]);
                    const float2 u1 = unpack2(acc[2 * r2 + 1]);
                    const ull nv = pack2(tanh_pre(u0.x + u0.y),
                                         tanh_pre(u1.x + u1.y));
                    if (p == 0) ns[r2] = nv; else s[8 + r2] = nv;
                }
            }
            #pragma unroll
            for (int r2 = 0; r2 < 8; r2++) s[r2] = ns[r2];

            // c = W_a2 @ s + b_a2 (in-lane, uniform weight loads)
            ull ca0 = 0ull, ca1 = 0ull, ca2 = 0ull, ca3 = 0ull;
            #pragma unroll
            for (int pq = 0; pq < 8; pq++) {
                const ull s0 = s[2 * pq], s1 = s[2 * pq + 1];
                const ulonglong2 w0 = *(const ulonglong2*)&wa2u[0][2 * pq];
                const ulonglong2 w1 = *(const ulonglong2*)&wa2u[1][2 * pq];
                const ulonglong2 w2 = *(const ulonglong2*)&wa2u[2][2 * pq];
                const ulonglong2 w3 = *(const ulonglong2*)&wa2u[3][2 * pq];
                ffma2(ca0, w0.x, s0); ffma2(ca0, w0.y, s1);
                ffma2(ca1, w1.x, s0); ffma2(ca1, w1.y, s1);
                ffma2(ca2, w2.x, s0); ffma2(ca2, w2.y, s1);
                ffma2(ca3, w3.x, s0); ffma2(ca3, w3.y, s1);
            }
            const float2 f0 = unpack2(ca0), f1 = unpack2(ca1);
            const float2 f2 = unpack2(ca2), f3 = unpack2(ca3);
            atomicAdd(op + (size_t)t * 4,     f0.x + f0.y + ba0);
            atomicAdd(op + (size_t)t * 4 + 1, f1.x + f1.y + ba1);
            atomicAdd(op + (size_t)t * 4 + 2, f2.x + f2.y + ba2v);
            atomicAdd(op + (size_t)t * 4 + 3, f3.x + f3.y + ba3);

            a_cur = a_nxt;
        }
    }
}

extern "C" void kernel_launch(void* const* d_in, const int* in_sizes, int n_in,
                              void* d_out, int out_size) {
    (void)in_sizes; (void)n_in; (void)out_size;
    transpose_kernel<<<dim3(T_LEN / 32, B_SZ / 32, 3), dim3(32, 8)>>>(
        (const int*)d_in[0], (const float*)d_in[1], (float*)d_out);
    memann_mod<<<128, 128>>>(
        (const float*)d_in[2], (const float*)d_in[3],
        (const float*)d_in[4], (const float*)d_in[5],
        (const float*)d_in[6], (const float*)d_in[7],
        (const float*)d_in[8], (const float*)d_in[9],
        (float*)d_out);
}